// round 3
// baseline (speedup 1.0000x reference)
#include <cuda_runtime.h>
#include <math.h>

#define BB    8
#define CC    192
#define HWs   16384
#define HEADS 8
#define DH    24
#define HID   384
#define TN    64          // pixels per block tile
#define TS    68          // smem row stride (pad 64 -> 68 to break bank conflicts)
#define KT    16          // K-chunk for GEMM
#define SAS   196         // sA row stride (pad 192 -> 196)

// -------------------- scratch (no allocs allowed) --------------------
__device__ float g_v[(size_t)BB * CC * HWs];        // v tensor, later reused as "fused"
__device__ float g_gram[BB * HEADS * DH * DH];      // unnormalized q.k^T
__device__ float g_ssq[2 * BB * CC];                // [0]: sum q^2 per (b,c); [1]: sum k^2
__device__ float g_attn[BB * HEADS * DH * DH];      // softmaxed attention

// -------------------- zero stats each replay --------------------
__global__ void k_zero() {
    int n = BB * HEADS * DH * DH;
    for (int i = blockIdx.x * blockDim.x + threadIdx.x; i < n; i += gridDim.x * blockDim.x)
        g_gram[i] = 0.f;
    int m = 2 * BB * CC;
    for (int i = blockIdx.x * blockDim.x + threadIdx.x; i < m; i += gridDim.x * blockDim.x)
        g_ssq[i] = 0.f;
}

// -------------------- shared GEMM tile: acc[12][4] += W[192 x 192(sub)] * sB[192 x 64] ---
// W row-major with leading dim lda; K-range = [koff, koff+192).
// Thread map: tx = tid&15 -> 4 consecutive pixels (tx*4+j), ty = tid>>4 -> 12 rows (ty*12+i).
__device__ __forceinline__ void gemm_tile(
    const float* __restrict__ W, int lda, int koff,
    const float* sB, float* sA,
    float acc[12][4], int tid, int tx, int ty)
{
    for (int k0 = 0; k0 < CC; k0 += KT) {
        __syncthreads();
        // stage W chunk [KT x 192] transposed into sA[kk][r]
#pragma unroll
        for (int it = 0; it < (KT * CC) / 256; ++it) {
            int idx = tid + it * 256;
            int r   = idx >> 4;
            int kk  = idx & 15;
            sA[kk * SAS + r] = W[(size_t)r * lda + koff + k0 + kk];
        }
        __syncthreads();
#pragma unroll
        for (int kk = 0; kk < KT; ++kk) {
            // B row is the global input channel (k0 + kk).
            float4 b4 = *(const float4*)&sB[(k0 + kk) * TS + tx * 4];
            float a[12];
#pragma unroll
            for (int i = 0; i < 3; ++i) {
                float4 a4 = *(const float4*)&sA[kk * SAS + ty * 12 + i * 4];
                a[i * 4 + 0] = a4.x; a[i * 4 + 1] = a4.y;
                a[i * 4 + 2] = a4.z; a[i * 4 + 3] = a4.w;
            }
#pragma unroll
            for (int i = 0; i < 12; ++i) {
                acc[i][0] = fmaf(a[i], b4.x, acc[i][0]);
                acc[i][1] = fmaf(a[i], b4.y, acc[i][1]);
                acc[i][2] = fmaf(a[i], b4.z, acc[i][2]);
                acc[i][3] = fmaf(a[i], b4.w, acc[i][3]);
            }
        }
    }
    __syncthreads();
}

// -------------------- K1: LN1 + QKV GEMMs + Gram/ssq + store V --------------------
extern __shared__ float smem[];

__global__ void __launch_bounds__(256, 1) k1(
    const float* __restrict__ image, const float* __restrict__ mask,
    const float* __restrict__ n1w, const float* __restrict__ n1b,
    const float* __restrict__ Wq, const float* __restrict__ Wk,
    const float* __restrict__ Wv)
{
    float* sBn   = smem;                    // [192][TS] : x -> xn -> k
    float* sBq   = sBn + CC * TS;           // [192][TS] : mask -> xn*m -> q
    float* sA    = sBq + CC * TS;           // [KT][SAS]
    float* sRed  = sA + KT * SAS;           // [2][4][64]
    float* sStat = sRed + 512;              // [2][64]

    int tid = threadIdx.x;
    int tx = tid & 15, ty = tid >> 4;
    int b  = blockIdx.y;
    int p0 = blockIdx.x * TN;

    const float* xg = image + (size_t)b * CC * HWs + p0;
    const float* mg = mask  + (size_t)b * CC * HWs + p0;

    // load x tile and mask tile
#pragma unroll
    for (int it = 0; it < 12; ++it) {
        int idx = tid + it * 256;
        int c = idx >> 4, pq = idx & 15;
        *(float4*)&sBn[c * TS + pq * 4] = *(const float4*)&xg[(size_t)c * HWs + pq * 4];
        *(float4*)&sBq[c * TS + pq * 4] = *(const float4*)&mg[(size_t)c * HWs + pq * 4];
    }
    __syncthreads();

    // per-pixel channel LN stats
    {
        int p = tid & 63, qt = tid >> 6;
        float s1 = 0.f, s2 = 0.f;
        for (int c = qt * 48; c < qt * 48 + 48; ++c) {
            float v = sBn[c * TS + p];
            s1 += v; s2 += v * v;
        }
        sRed[qt * 64 + p] = s1;
        sRed[256 + qt * 64 + p] = s2;
    }
    __syncthreads();
    if (tid < 64) {
        float a = 0.f, s = 0.f;
        for (int q = 0; q < 4; ++q) { a += sRed[q * 64 + tid]; s += sRed[256 + q * 64 + tid]; }
        float mu = a * (1.f / 192.f);
        float var = s * (1.f / 192.f) - mu * mu;
        sStat[tid]      = mu;
        sStat[64 + tid] = rsqrtf(var + 1e-5f);
    }
    __syncthreads();

    // normalize: sBn = xn, sBq = xn * max(mask, 0.1)
#pragma unroll
    for (int it = 0; it < 12; ++it) {
        int idx = tid + it * 256;
        int c = idx >> 4, pq = idx & 15;
        float wc = n1w[c], bc = n1b[c];
#pragma unroll
        for (int j = 0; j < 4; ++j) {
            int pp = pq * 4 + j;
            float xn = (sBn[c * TS + pp] - sStat[pp]) * sStat[64 + pp] * wc + bc;
            float m  = fmaxf(sBq[c * TS + pp], 0.1f);
            sBn[c * TS + pp] = xn;
            sBq[c * TS + pp] = xn * m;
        }
    }
    __syncthreads();

    float acc[12][4];

    // V = Wv @ xn  -> global scratch
#pragma unroll
    for (int i = 0; i < 12; ++i) { acc[i][0]=acc[i][1]=acc[i][2]=acc[i][3]=0.f; }
    gemm_tile(Wv, CC, 0, sBn, sA, acc, tid, tx, ty);
#pragma unroll
    for (int i = 0; i < 12; ++i) {
        int r = ty * 12 + i;
        float4 o = make_float4(acc[i][0], acc[i][1], acc[i][2], acc[i][3]);
        *(float4*)&g_v[((size_t)(b * CC + r)) * HWs + p0 + tx * 4] = o;
    }

    // Q = Wq @ (xn*m)  -> overwrite sBq
#pragma unroll
    for (int i = 0; i < 12; ++i) { acc[i][0]=acc[i][1]=acc[i][2]=acc[i][3]=0.f; }
    gemm_tile(Wq, CC, 0, sBq, sA, acc, tid, tx, ty);
#pragma unroll
    for (int i = 0; i < 12; ++i) {
        int r = ty * 12 + i;
#pragma unroll
        for (int j = 0; j < 4; ++j) sBq[r * TS + tx * 4 + j] = acc[i][j];
    }
    __syncthreads();

    // K = Wk @ xn  -> overwrite sBn
#pragma unroll
    for (int i = 0; i < 12; ++i) { acc[i][0]=acc[i][1]=acc[i][2]=acc[i][3]=0.f; }
    gemm_tile(Wk, CC, 0, sBn, sA, acc, tid, tx, ty);
#pragma unroll
    for (int i = 0; i < 12; ++i) {
        int r = ty * 12 + i;
#pragma unroll
        for (int j = 0; j < 4; ++j) sBn[r * TS + tx * 4 + j] = acc[i][j];
    }
    __syncthreads();

    // Gram + sumsq. Thread t<192 owns q-row t; d-loop shared across lanes -> k reads broadcast.
    if (tid < 192) {
        int h  = tid / DH;
        int cq = tid % DH;
        float gacc[DH];
#pragma unroll
        for (int d = 0; d < DH; ++d) gacc[d] = 0.f;
        float qsq = 0.f;
        for (int pc = 0; pc < 8; ++pc) {
            float4 q0 = *(const float4*)&sBq[tid * TS + pc * 8];
            float4 q1 = *(const float4*)&sBq[tid * TS + pc * 8 + 4];
            qsq += q0.x*q0.x + q0.y*q0.y + q0.z*q0.z + q0.w*q0.w
                 + q1.x*q1.x + q1.y*q1.y + q1.z*q1.z + q1.w*q1.w;
#pragma unroll
            for (int d = 0; d < DH; ++d) {
                int rk = h * DH + d;
                float4 k0 = *(const float4*)&sBn[rk * TS + pc * 8];
                float4 k1 = *(const float4*)&sBn[rk * TS + pc * 8 + 4];
                gacc[d] += q0.x*k0.x + q0.y*k0.y + q0.z*k0.z + q0.w*k0.w
                         + q1.x*k1.x + q1.y*k1.y + q1.z*k1.z + q1.w*k1.w;
            }
        }
#pragma unroll
        for (int d = 0; d < DH; ++d)
            atomicAdd(&g_gram[((b * HEADS + h) * DH + cq) * DH + d], gacc[d]);
        atomicAdd(&g_ssq[b * CC + tid], qsq);

        float ksq = 0.f;
        for (int pc = 0; pc < 16; ++pc) {
            float4 kk4 = *(const float4*)&sBn[tid * TS + pc * 4];
            ksq += kk4.x*kk4.x + kk4.y*kk4.y + kk4.z*kk4.z + kk4.w*kk4.w;
        }
        atomicAdd(&g_ssq[BB * CC + b * CC + tid], ksq);
    }
}

// -------------------- K2: normalize + softmax -> attn --------------------
__global__ void k2(const float* __restrict__ temp)
{
    int bh = blockIdx.x;
    int b = bh / HEADS, h = bh % HEADS;
    int cq = threadIdx.x;
    if (cq >= DH) return;
    float t = temp[h];
    float nq = fmaxf(sqrtf(g_ssq[b * CC + h * DH + cq]), 1e-12f);
    float lg[DH];
    float mx = -1e30f;
#pragma unroll
    for (int d = 0; d < DH; ++d) {
        float nk = fmaxf(sqrtf(g_ssq[BB * CC + b * CC + h * DH + d]), 1e-12f);
        float v = g_gram[((b * HEADS + h) * DH + cq) * DH + d] * t / (nq * nk);
        lg[d] = v;
        mx = fmaxf(mx, v);
    }
    float s = 0.f;
#pragma unroll
    for (int d = 0; d < DH; ++d) { lg[d] = expf(lg[d] - mx); s += lg[d]; }
    float inv = 1.f / s;
#pragma unroll
    for (int d = 0; d < DH; ++d)
        g_attn[((b * HEADS + h) * DH + cq) * DH + d] = lg[d] * inv;
}

// -------------------- K3a: attn@v, Wo, +image -> fused (in place over g_v) ----------
__global__ void __launch_bounds__(256, 1) k3a(
    const float* __restrict__ image, const float* __restrict__ Wo)
{
    float* sV  = smem;                  // [192][TS]
    float* sO  = sV + CC * TS;          // [192][TS]
    float* sA  = sO + CC * TS;          // [KT][SAS]
    float* sAt = sA + KT * SAS;         // [8*24*24]

    int tid = threadIdx.x;
    int tx = tid & 15, ty = tid >> 4;
    int b  = blockIdx.y;
    int p0 = blockIdx.x * TN;

#pragma unroll
    for (int it = 0; it < 18; ++it) {
        int idx = tid + it * 256;       // 4608 attn entries
        sAt[idx] = g_attn[b * HEADS * DH * DH + idx];
    }
#pragma unroll
    for (int it = 0; it < 12; ++it) {
        int idx = tid + it * 256;
        int c = idx >> 4, pq = idx & 15;
        *(float4*)&sV[c * TS + pq * 4] =
            *(const float4*)&g_v[((size_t)(b * CC + c)) * HWs + p0 + pq * 4];
    }
    __syncthreads();

    // out1 = attn @ v (per head)
#pragma unroll
    for (int i = 0; i < 12; ++i) {
        int r = ty * 12 + i;
        int h = r / DH, cq = r % DH;
        const float* at = &sAt[(h * DH + cq) * DH];
        float4 o = make_float4(0.f, 0.f, 0.f, 0.f);
#pragma unroll
        for (int d = 0; d < DH; ++d) {
            float a = at[d];
            float4 v4 = *(const float4*)&sV[(h * DH + d) * TS + tx * 4];
            o.x = fmaf(a, v4.x, o.x); o.y = fmaf(a, v4.y, o.y);
            o.z = fmaf(a, v4.z, o.z); o.w = fmaf(a, v4.w, o.w);
        }
        *(float4*)&sO[r * TS + tx * 4] = o;
    }
    __syncthreads();

    float acc[12][4];
#pragma unroll
    for (int i = 0; i < 12; ++i) { acc[i][0]=acc[i][1]=acc[i][2]=acc[i][3]=0.f; }
    gemm_tile(Wo, CC, 0, sO, sA, acc, tid, tx, ty);

#pragma unroll
    for (int i = 0; i < 12; ++i) {
        int r = ty * 12 + i;
        float4 im = *(const float4*)&image[((size_t)(b * CC + r)) * HWs + p0 + tx * 4];
        float4 f = make_float4(acc[i][0] + im.x, acc[i][1] + im.y,
                               acc[i][2] + im.z, acc[i][3] + im.w);
        *(float4*)&g_v[((size_t)(b * CC + r)) * HWs + p0 + tx * 4] = f;  // fused
    }
}

// -------------------- K3b: LN2 + MLP + residual -> out --------------------
__global__ void __launch_bounds__(256, 1) k3b(
    const float* __restrict__ n2w, const float* __restrict__ n2b,
    const float* __restrict__ fc1w, const float* __restrict__ fc1b,
    const float* __restrict__ fc2w, const float* __restrict__ fc2b,
    float* __restrict__ out)
{
    float* sX    = smem;                // fused [192][TS]
    float* sXn   = sX + CC * TS;        // LN2(fused)
    float* sM    = sXn + CC * TS;       // GELU mid (one 192-half at a time)
    float* sA    = sM + CC * TS;
    float* sRed  = sA + KT * SAS;
    float* sStat = sRed + 512;

    int tid = threadIdx.x;
    int tx = tid & 15, ty = tid >> 4;
    int b  = blockIdx.y;
    int p0 = blockIdx.x * TN;

#pragma unroll
    for (int it = 0; it < 12; ++it) {
        int idx = tid + it * 256;
        int c = idx >> 4, pq = idx & 15;
        *(float4*)&sX[c * TS + pq * 4] =
            *(const float4*)&g_v[((size_t)(b * CC + c)) * HWs + p0 + pq * 4];
    }
    __syncthreads();

    {
        int p = tid & 63, qt = tid >> 6;
        float s1 = 0.f, s2 = 0.f;
        for (int c = qt * 48; c < qt * 48 + 48; ++c) {
            float v = sX[c * TS + p];
            s1 += v; s2 += v * v;
        }
        sRed[qt * 64 + p] = s1;
        sRed[256 + qt * 64 + p] = s2;
    }
    __syncthreads();
    if (tid < 64) {
        float a = 0.f, s = 0.f;
        for (int q = 0; q < 4; ++q) { a += sRed[q * 64 + tid]; s += sRed[256 + q * 64 + tid]; }
        float mu = a * (1.f / 192.f);
        float var = s * (1.f / 192.f) - mu * mu;
        sStat[tid]      = mu;
        sStat[64 + tid] = rsqrtf(var + 1e-5f);
    }
    __syncthreads();

#pragma unroll
    for (int it = 0; it < 12; ++it) {
        int idx = tid + it * 256;
        int c = idx >> 4, pq = idx & 15;
        float wc = n2w[c], bc = n2b[c];
#pragma unroll
        for (int j = 0; j < 4; ++j) {
            int pp = pq * 4 + j;
            sXn[c * TS + pp] = (sX[c * TS + pp] - sStat[pp]) * sStat[64 + pp] * wc + bc;
        }
    }
    __syncthreads();

    float acc2[12][4];
#pragma unroll
    for (int i = 0; i < 12; ++i) {
        float bv = fc2b[ty * 12 + i];
        acc2[i][0] = bv; acc2[i][1] = bv; acc2[i][2] = bv; acc2[i][3] = bv;
    }

    for (int half = 0; half < 2; ++half) {
        float acc1[12][4];
#pragma unroll
        for (int i = 0; i < 12; ++i) { acc1[i][0]=acc1[i][1]=acc1[i][2]=acc1[i][3]=0.f; }
        gemm_tile(fc1w + (size_t)half * 192 * CC, CC, 0, sXn, sA, acc1, tid, tx, ty);
        // bias + exact GELU -> sM
#pragma unroll
        for (int i = 0; i < 12; ++i) {
            int r = ty * 12 + i;
            float bv = fc1b[half * 192 + r];
#pragma unroll
            for (int j = 0; j < 4; ++j) {
                float x = acc1[i][j] + bv;
                sM[r * TS + tx * 4 + j] = 0.5f * x * (1.f + erff(x * 0.70710678118f));
            }
        }
        __syncthreads();
        gemm_tile(fc2w, HID, half * 192, sM, sA, acc2, tid, tx, ty);
    }

#pragma unroll
    for (int i = 0; i < 12; ++i) {
        int r = ty * 12 + i;
        float4 xr = *(const float4*)&sX[r * TS + tx * 4];
        float4 o = make_float4(acc2[i][0] + xr.x, acc2[i][1] + xr.y,
                               acc2[i][2] + xr.z, acc2[i][3] + xr.w);
        *(float4*)&out[((size_t)(b * CC + r)) * HWs + p0 + tx * 4] = o;
    }
}

// -------------------- launch --------------------
extern "C" void kernel_launch(void* const* d_in, const int* in_sizes, int n_in,
                              void* d_out, int out_size)
{
    const float* image = (const float*)d_in[0];
    const float* mask  = (const float*)d_in[1];
    const float* n1w   = (const float*)d_in[2];
    const float* n1b   = (const float*)d_in[3];
    const float* Wq    = (const float*)d_in[4];
    const float* Wk    = (const float*)d_in[5];
    const float* Wv    = (const float*)d_in[6];
    const float* Wo    = (const float*)d_in[7];
    const float* temp  = (const float*)d_in[8];
    const float* n2w   = (const float*)d_in[9];
    const float* n2b   = (const float*)d_in[10];
    const float* fc1w  = (const float*)d_in[11];
    const float* fc1b  = (const float*)d_in[12];
    const float* fc2w  = (const float*)d_in[13];
    const float* fc2b  = (const float*)d_in[14];
    float* out = (float*)d_out;

    size_t smem1  = (size_t)(2 * CC * TS + KT * SAS + 512 + 128) * sizeof(float);
    size_t smem3a = (size_t)(2 * CC * TS + KT * SAS + HEADS * DH * DH) * sizeof(float);
    size_t smem3b = (size_t)(3 * CC * TS + KT * SAS + 512 + 128) * sizeof(float);

    cudaFuncSetAttribute(k1,  cudaFuncAttributeMaxDynamicSharedMemorySize, (int)smem1);
    cudaFuncSetAttribute(k3a, cudaFuncAttributeMaxDynamicSharedMemorySize, (int)smem3a);
    cudaFuncSetAttribute(k3b, cudaFuncAttributeMaxDynamicSharedMemorySize, (int)smem3b);

    dim3 grid(HWs / TN, BB);

    k_zero<<<64, 256>>>();
    k1 <<<grid, 256, smem1 >>>(image, mask, n1w, n1b, Wq, Wk, Wv);
    k2 <<<BB * HEADS, 32>>>(temp);
    k3a<<<grid, 256, smem3a>>>(image, Wo);
    k3b<<<grid, 256, smem3b>>>(n2w, n2b, fc1w, fc1b, fc2w, fc2b, out);
}

// round 6
// speedup vs baseline: 1.9015x; 1.9015x over previous
#include <cuda_runtime.h>
#include <cuda_bf16.h>
#include <cstdint>
#include <cstddef>
#include <math.h>

#define BB    8
#define CC    192
#define HWs   16384
#define HEADS 8
#define DH    24
#define HID   384
#define TN    64          // pixels per block tile
#define TS    68          // fp32 tile row stride (floats)
#define TNH   72          // bf16 activation tile row stride (elements)
#define WST   200         // bf16 weight tile row stride (elements)

// -------------------- scratch (no allocs allowed) --------------------
__device__ float         g_v[(size_t)BB * CC * HWs];     // fused (fp32), written by k3a
__device__ __nv_bfloat16 g_vh[(size_t)BB * CC * HWs];    // V (bf16), written by k1
__device__ float g_gram[BB * HEADS * DH * DH];
__device__ float g_ssq[2 * BB * CC];
__device__ float g_attn[BB * HEADS * DH * DH];

// -------------------- zero stats each replay --------------------
__global__ void k_zero() {
    int n = BB * HEADS * DH * DH;
    for (int i = blockIdx.x * blockDim.x + threadIdx.x; i < n; i += gridDim.x * blockDim.x)
        g_gram[i] = 0.f;
    int m = 2 * BB * CC;
    for (int i = blockIdx.x * blockDim.x + threadIdx.x; i < m; i += gridDim.x * blockDim.x)
        g_ssq[i] = 0.f;
}

// -------------------- mma helpers --------------------
__device__ __forceinline__ unsigned int su32(const void* p) {
    return (unsigned int)__cvta_generic_to_shared(p);
}
__device__ __forceinline__ void ldsm4(unsigned int* r, unsigned int a) {
    asm volatile("ldmatrix.sync.aligned.m8n8.x4.shared.b16 {%0,%1,%2,%3},[%4];"
        : "=r"(r[0]), "=r"(r[1]), "=r"(r[2]), "=r"(r[3]) : "r"(a));
}
__device__ __forceinline__ void ldsm4t(unsigned int* r, unsigned int a) {
    asm volatile("ldmatrix.sync.aligned.m8n8.x4.trans.shared.b16 {%0,%1,%2,%3},[%4];"
        : "=r"(r[0]), "=r"(r[1]), "=r"(r[2]), "=r"(r[3]) : "r"(a));
}
__device__ __forceinline__ void mma16816(float* c, const unsigned int* a,
                                         unsigned int b0, unsigned int b1) {
    asm volatile("mma.sync.aligned.m16n8k16.row.col.f32.bf16.bf16.f32 "
        "{%0,%1,%2,%3},{%4,%5,%6,%7},{%8,%9},{%0,%1,%2,%3};"
        : "+f"(c[0]), "+f"(c[1]), "+f"(c[2]), "+f"(c[3])
        : "r"(a[0]), "r"(a[1]), "r"(a[2]), "r"(a[3]), "r"(b0), "r"(b1));
}

// Stage a 192x192 fp32 weight slice (row stride ldw, col offset koff) into bf16 sW[r*WST+k].
__device__ __forceinline__ void stageW(const float* __restrict__ W, int ldw, int koff,
                                       __nv_bfloat16* sW, int tid) {
    for (int i = tid; i < CC * (CC / 2); i += 256) {
        int r = i / (CC / 2);
        int k2 = (i % (CC / 2)) * 2;
        float2 v = *(const float2*)&W[(size_t)r * ldw + koff + k2];
        *(__nv_bfloat162*)&sW[r * WST + k2] = __float22bfloat162_rn(v);
    }
}

// C[192x64] = W[192x192] * B[192x64]; warp layout 4(m) x 2(n); per-warp 3 m16 x 4 n8 tiles.
__device__ __forceinline__ void mma_gemm(const __nv_bfloat16* sW, const __nv_bfloat16* sBH,
                                         float acc[3][4][4], int lane, int m_base, int n_base) {
    unsigned int aBase = su32(sW) +
        (unsigned int)(((m_base + (lane & 15)) * WST + ((lane >> 4) * 8)) * 2);
    unsigned int bBase = su32(sBH) +
        (unsigned int)(((((lane & 7) + ((lane >> 3) & 1) * 8)) * TNH + n_base + (lane >> 4) * 8) * 2);
#pragma unroll
    for (int ks = 0; ks < CC / 16; ++ks) {
        unsigned int A[3][4];
#pragma unroll
        for (int mi = 0; mi < 3; ++mi)
            ldsm4(A[mi], aBase + (unsigned int)((mi * 16 * WST + ks * 16) * 2));
        unsigned int Bm[2][4];
#pragma unroll
        for (int bi = 0; bi < 2; ++bi)
            ldsm4t(Bm[bi], bBase + (unsigned int)((ks * 16 * TNH + bi * 16) * 2));
#pragma unroll
        for (int mi = 0; mi < 3; ++mi) {
            mma16816(acc[mi][0], A[mi], Bm[0][0], Bm[0][1]);
            mma16816(acc[mi][1], A[mi], Bm[0][2], Bm[0][3]);
            mma16816(acc[mi][2], A[mi], Bm[1][0], Bm[1][1]);
            mma16816(acc[mi][3], A[mi], Bm[1][2], Bm[1][3]);
        }
    }
}

__device__ __forceinline__ void zacc(float acc[3][4][4]) {
#pragma unroll
    for (int mi = 0; mi < 3; ++mi)
#pragma unroll
        for (int ni = 0; ni < 4; ++ni) {
            acc[mi][ni][0] = 0.f; acc[mi][ni][1] = 0.f;
            acc[mi][ni][2] = 0.f; acc[mi][ni][3] = 0.f;
        }
}

// -------------------- K1: LN1 + QKV mma GEMMs + Gram/ssq + store V(bf16) --------------------
__global__ void __launch_bounds__(256, 1) k1(
    const float* __restrict__ image, const float* __restrict__ mask,
    const float* __restrict__ n1w, const float* __restrict__ n1b,
    const float* __restrict__ Wq, const float* __restrict__ Wk,
    const float* __restrict__ Wv)
{
    extern __shared__ float smem[];
    float*         sX   = smem;                                   // [192][TS] fp32
    __nv_bfloat16* sQH  = (__nv_bfloat16*)(smem + CC * TS);       // [192][TNH]
    __nv_bfloat16* sKH  = sQH + CC * TNH;                         // [192][TNH]
    __nv_bfloat16* sW   = sKH + CC * TNH;                         // [192][WST]
    float*         sRed = (float*)(sW + CC * WST);                // 512
    float*         sStat= sRed + 512;                             // 128

    int tid  = threadIdx.x;
    int lane = tid & 31, w = tid >> 5;
    int m_base = (w >> 1) * 48, n_base = (w & 1) * 32;
    int g = lane >> 2, t2 = (lane & 3) * 2;
    int b  = blockIdx.y;
    int p0 = blockIdx.x * TN;

    const float* xg = image + (size_t)b * CC * HWs + p0;
    const float* mg = mask  + (size_t)b * CC * HWs + p0;

    // load x tile (fp32)
#pragma unroll
    for (int it = 0; it < 12; ++it) {
        int idx = tid + it * 256;
        int c = idx >> 4, pq = idx & 15;
        *(float4*)&sX[c * TS + pq * 4] = *(const float4*)&xg[(size_t)c * HWs + pq * 4];
    }
    __syncthreads();

    // per-pixel channel LN stats
    {
        int p = tid & 63, qt = tid >> 6;
        float s1 = 0.f, s2 = 0.f;
        for (int c = qt * 48; c < qt * 48 + 48; ++c) {
            float v = sX[c * TS + p];
            s1 += v; s2 += v * v;
        }
        sRed[qt * 64 + p] = s1;
        sRed[256 + qt * 64 + p] = s2;
    }
    __syncthreads();
    if (tid < 64) {
        float a = 0.f, s = 0.f;
        for (int q = 0; q < 4; ++q) { a += sRed[q * 64 + tid]; s += sRed[256 + q * 64 + tid]; }
        float mu = a * (1.f / 192.f);
        float var = s * (1.f / 192.f) - mu * mu;
        sStat[tid]      = mu;
        sStat[64 + tid] = rsqrtf(var + 1e-5f);
    }
    __syncthreads();

    // normalize: sKH = bf16(xn), sQH = bf16(xn * max(mask, 0.1))
#pragma unroll
    for (int it = 0; it < 12; ++it) {
        int idx = tid + it * 256;
        int c = idx >> 4, pq = idx & 15;
        float wc = n1w[c], bc = n1b[c];
        float4 m4 = *(const float4*)&mg[(size_t)c * HWs + pq * 4];
        float xn[4], qv[4];
        float mm[4] = {m4.x, m4.y, m4.z, m4.w};
#pragma unroll
        for (int j = 0; j < 4; ++j) {
            int pp = pq * 4 + j;
            xn[j] = (sX[c * TS + pp] - sStat[pp]) * sStat[64 + pp] * wc + bc;
            qv[j] = xn[j] * fmaxf(mm[j], 0.1f);
        }
        *(__nv_bfloat162*)&sKH[c * TNH + pq * 4]     = __floats2bfloat162_rn(xn[0], xn[1]);
        *(__nv_bfloat162*)&sKH[c * TNH + pq * 4 + 2] = __floats2bfloat162_rn(xn[2], xn[3]);
        *(__nv_bfloat162*)&sQH[c * TNH + pq * 4]     = __floats2bfloat162_rn(qv[0], qv[1]);
        *(__nv_bfloat162*)&sQH[c * TNH + pq * 4 + 2] = __floats2bfloat162_rn(qv[2], qv[3]);
    }
    __syncthreads();

    float acc[3][4][4];

    // ---- V = Wv @ xn -> g_vh (bf16) ----
    stageW(Wv, CC, 0, sW, tid);
    __syncthreads();
    zacc(acc);
    mma_gemm(sW, sKH, acc, lane, m_base, n_base);
#pragma unroll
    for (int mi = 0; mi < 3; ++mi)
#pragma unroll
        for (int ni = 0; ni < 4; ++ni) {
            int r0 = m_base + mi * 16 + g, c = n_base + ni * 8 + t2;
            *(__nv_bfloat162*)&g_vh[((size_t)(b * CC + r0)) * HWs + p0 + c] =
                __floats2bfloat162_rn(acc[mi][ni][0], acc[mi][ni][1]);
            *(__nv_bfloat162*)&g_vh[((size_t)(b * CC + r0 + 8)) * HWs + p0 + c] =
                __floats2bfloat162_rn(acc[mi][ni][2], acc[mi][ni][3]);
        }
    __syncthreads();

    // ---- Q = Wq @ (xn*m) ----
    stageW(Wq, CC, 0, sW, tid);
    __syncthreads();
    zacc(acc);
    mma_gemm(sW, sQH, acc, lane, m_base, n_base);
    __syncthreads();              // all warps done reading sQH/sW
    // write Q (bf16) back into sQH
#pragma unroll
    for (int mi = 0; mi < 3; ++mi)
#pragma unroll
        for (int ni = 0; ni < 4; ++ni) {
            int r0 = m_base + mi * 16 + g, c = n_base + ni * 8 + t2;
            *(__nv_bfloat162*)&sQH[r0 * TNH + c] =
                __floats2bfloat162_rn(acc[mi][ni][0], acc[mi][ni][1]);
            *(__nv_bfloat162*)&sQH[(r0 + 8) * TNH + c] =
                __floats2bfloat162_rn(acc[mi][ni][2], acc[mi][ni][3]);
        }

    // ---- K = Wk @ xn ----
    stageW(Wk, CC, 0, sW, tid);
    __syncthreads();
    zacc(acc);
    mma_gemm(sW, sKH, acc, lane, m_base, n_base);
    __syncthreads();              // all warps done reading sKH
#pragma unroll
    for (int mi = 0; mi < 3; ++mi)
#pragma unroll
        for (int ni = 0; ni < 4; ++ni) {
            int r0 = m_base + mi * 16 + g, c = n_base + ni * 8 + t2;
            *(__nv_bfloat162*)&sKH[r0 * TNH + c] =
                __floats2bfloat162_rn(acc[mi][ni][0], acc[mi][ni][1]);
            *(__nv_bfloat162*)&sKH[(r0 + 8) * TNH + c] =
                __floats2bfloat162_rn(acc[mi][ni][2], acc[mi][ni][3]);
        }
    __syncthreads();

    // ---- Gram + sumsq (fp32 accumulate over bf16 q/k) ----
    if (tid < CC) {
        int h  = tid / DH;
        int cq = tid % DH;
        float gacc[DH];
#pragma unroll
        for (int d = 0; d < DH; ++d) gacc[d] = 0.f;
        float qsq = 0.f;
        for (int pc = 0; pc < 8; ++pc) {
            float q[8];
#pragma unroll
            for (int j = 0; j < 4; ++j) {
                float2 v = __bfloat1622float2(
                    *(const __nv_bfloat162*)&sQH[tid * TNH + pc * 8 + j * 2]);
                q[j * 2] = v.x; q[j * 2 + 1] = v.y;
                qsq += v.x * v.x + v.y * v.y;
            }
#pragma unroll
            for (int d = 0; d < DH; ++d) {
                const __nv_bfloat162* kr =
                    (const __nv_bfloat162*)&sKH[(h * DH + d) * TNH + pc * 8];
                float s = 0.f;
#pragma unroll
                for (int j = 0; j < 4; ++j) {
                    float2 kv = __bfloat1622float2(kr[j]);
                    s += q[j * 2] * kv.x + q[j * 2 + 1] * kv.y;
                }
                gacc[d] += s;
            }
        }
#pragma unroll
        for (int d = 0; d < DH; ++d)
            atomicAdd(&g_gram[((b * HEADS + h) * DH + cq) * DH + d], gacc[d]);
        atomicAdd(&g_ssq[b * CC + tid], qsq);

        float ksq = 0.f;
        const __nv_bfloat162* krow = (const __nv_bfloat162*)&sKH[tid * TNH];
#pragma unroll
        for (int j = 0; j < 32; ++j) {
            float2 kv = __bfloat1622float2(krow[j]);
            ksq += kv.x * kv.x + kv.y * kv.y;
        }
        atomicAdd(&g_ssq[BB * CC + b * CC + tid], ksq);
    }
}

// -------------------- K2: normalize + softmax -> attn --------------------
__global__ void k2(const float* __restrict__ temp)
{
    int bh = blockIdx.x;
    int b = bh / HEADS, h = bh % HEADS;
    int cq = threadIdx.x;
    if (cq >= DH) return;
    float t = temp[h];
    float nq = fmaxf(sqrtf(g_ssq[b * CC + h * DH + cq]), 1e-12f);
    float lg[DH];
    float mx = -1e30f;
#pragma unroll
    for (int d = 0; d < DH; ++d) {
        float nk = fmaxf(sqrtf(g_ssq[BB * CC + b * CC + h * DH + d]), 1e-12f);
        float v = g_gram[((b * HEADS + h) * DH + cq) * DH + d] * t / (nq * nk);
        lg[d] = v;
        mx = fmaxf(mx, v);
    }
    float s = 0.f;
#pragma unroll
    for (int d = 0; d < DH; ++d) { lg[d] = expf(lg[d] - mx); s += lg[d]; }
    float inv = 1.f / s;
#pragma unroll
    for (int d = 0; d < DH; ++d)
        g_attn[((b * HEADS + h) * DH + cq) * DH + d] = lg[d] * inv;
}

// -------------------- K3a: attn@v, Wo (mma), +image -> fused (g_v fp32) --------------------
__global__ void __launch_bounds__(256, 1) k3a(
    const float* __restrict__ image, const float* __restrict__ Wo)
{
    extern __shared__ float smem[];
    __nv_bfloat16* sVH = (__nv_bfloat16*)smem;        // [192][TNH]
    __nv_bfloat16* sOH = sVH + CC * TNH;              // [192][TNH]
    __nv_bfloat16* sW  = sOH + CC * TNH;              // [192][WST]
    float*         sAt = (float*)(sW + CC * WST);     // [8*24*24]

    int tid  = threadIdx.x;
    int lane = tid & 31, w = tid >> 5;
    int m_base = (w >> 1) * 48, n_base = (w & 1) * 32;
    int g = lane >> 2, t2 = (lane & 3) * 2;
    int tx = tid & 15, ty = tid >> 4;
    int b  = blockIdx.y;
    int p0 = blockIdx.x * TN;

#pragma unroll
    for (int it = 0; it < 18; ++it) {
        int idx = tid + it * 256;
        sAt[idx] = g_attn[b * HEADS * DH * DH + idx];
    }
    // load V bf16 tile (coalesced u32 copies)
    for (int i = tid; i < CC * 32; i += 256) {
        int c = i >> 5, j = i & 31;
        ((unsigned int*)sVH)[c * (TNH / 2) + j] =
            *(const unsigned int*)(g_vh + ((size_t)(b * CC + c)) * HWs + p0 + 2 * j);
    }
    __syncthreads();

    // out1 = attn @ v (fp32 accumulate) -> sOH bf16
#pragma unroll
    for (int i = 0; i < 12; ++i) {
        int r = ty * 12 + i, h = r / DH, cq = r % DH;
        const float* at = &sAt[(h * DH + cq) * DH];
        float o0 = 0.f, o1 = 0.f, o2 = 0.f, o3 = 0.f;
#pragma unroll
        for (int d = 0; d < DH; ++d) {
            float a = at[d];
            const __nv_bfloat162* vr =
                (const __nv_bfloat162*)&sVH[(h * DH + d) * TNH + tx * 4];
            float2 v0 = __bfloat1622float2(vr[0]);
            float2 v1 = __bfloat1622float2(vr[1]);
            o0 = fmaf(a, v0.x, o0); o1 = fmaf(a, v0.y, o1);
            o2 = fmaf(a, v1.x, o2); o3 = fmaf(a, v1.y, o3);
        }
        *(__nv_bfloat162*)&sOH[r * TNH + tx * 4]     = __floats2bfloat162_rn(o0, o1);
        *(__nv_bfloat162*)&sOH[r * TNH + tx * 4 + 2] = __floats2bfloat162_rn(o2, o3);
    }
    stageW(Wo, CC, 0, sW, tid);
    __syncthreads();

    float acc[3][4][4];
    zacc(acc);
    mma_gemm(sW, sOH, acc, lane, m_base, n_base);

    // fused = Wo@out1 + image -> g_v (fp32)
#pragma unroll
    for (int mi = 0; mi < 3; ++mi)
#pragma unroll
        for (int ni = 0; ni < 4; ++ni) {
            int r0 = m_base + mi * 16 + g, c = n_base + ni * 8 + t2;
            size_t o0 = ((size_t)(b * CC + r0)) * HWs + p0 + c;
            size_t o1 = ((size_t)(b * CC + r0 + 8)) * HWs + p0 + c;
            float2 im0 = *(const float2*)&image[o0];
            float2 im1 = *(const float2*)&image[o1];
            float2 f0 = make_float2(acc[mi][ni][0] + im0.x, acc[mi][ni][1] + im0.y);
            float2 f1 = make_float2(acc[mi][ni][2] + im1.x, acc[mi][ni][3] + im1.y);
            *(float2*)&g_v[o0] = f0;
            *(float2*)&g_v[o1] = f1;
        }
}

// -------------------- K3b: LN2 + MLP (mma) + residual -> out --------------------
__global__ void __launch_bounds__(256, 1) k3b(
    const float* __restrict__ n2w, const float* __restrict__ n2b,
    const float* __restrict__ fc1w, const float* __restrict__ fc1b,
    const float* __restrict__ fc2w, const float* __restrict__ fc2b,
    float* __restrict__ out)
{
    extern __shared__ float smem[];
    float*         sX   = smem;                              // [192][TS] fused fp32
    __nv_bfloat16* sXnH = (__nv_bfloat16*)(smem + CC * TS);  // [192][TNH] LN2 bf16
    __nv_bfloat16* sMH  = sXnH + CC * TNH;                   // [192][TNH] GELU mid bf16
    __nv_bfloat16* sW   = sMH + CC * TNH;                    // [192][WST]
    float*         sRed = (float*)(sW + CC * WST);
    float*         sStat= sRed + 512;

    int tid  = threadIdx.x;
    int lane = tid & 31, w = tid >> 5;
    int m_base = (w >> 1) * 48, n_base = (w & 1) * 32;
    int g = lane >> 2, t2 = (lane & 3) * 2;
    int b  = blockIdx.y;
    int p0 = blockIdx.x * TN;

#pragma unroll
    for (int it = 0; it < 12; ++it) {
        int idx = tid + it * 256;
        int c = idx >> 4, pq = idx & 15;
        *(float4*)&sX[c * TS + pq * 4] =
            *(const float4*)&g_v[((size_t)(b * CC + c)) * HWs + p0 + pq * 4];
    }
    __syncthreads();

    {
        int p = tid & 63, qt = tid >> 6;
        float s1 = 0.f, s2 = 0.f;
        for (int c = qt * 48; c < qt * 48 + 48; ++c) {
            float v = sX[c * TS + p];
            s1 += v; s2 += v * v;
        }
        sRed[qt * 64 + p] = s1;
        sRed[256 + qt * 64 + p] = s2;
    }
    __syncthreads();
    if (tid < 64) {
        float a = 0.f, s = 0.f;
        for (int q = 0; q < 4; ++q) { a += sRed[q * 64 + tid]; s += sRed[256 + q * 64 + tid]; }
        float mu = a * (1.f / 192.f);
        float var = s * (1.f / 192.f) - mu * mu;
        sStat[tid]      = mu;
        sStat[64 + tid] = rsqrtf(var + 1e-5f);
    }
    __syncthreads();

#pragma unroll
    for (int it = 0; it < 12; ++it) {
        int idx = tid + it * 256;
        int c = idx >> 4, pq = idx & 15;
        float wc = n2w[c], bc = n2b[c];
        float xn[4];
#pragma unroll
        for (int j = 0; j < 4; ++j) {
            int pp = pq * 4 + j;
            xn[j] = (sX[c * TS + pp] - sStat[pp]) * sStat[64 + pp] * wc + bc;
        }
        *(__nv_bfloat162*)&sXnH[c * TNH + pq * 4]     = __floats2bfloat162_rn(xn[0], xn[1]);
        *(__nv_bfloat162*)&sXnH[c * TNH + pq * 4 + 2] = __floats2bfloat162_rn(xn[2], xn[3]);
    }
    __syncthreads();

    // acc2 initialized with fc2 bias
    float acc2[3][4][4];
#pragma unroll
    for (int mi = 0; mi < 3; ++mi) {
        float b0v = fc2b[m_base + mi * 16 + g];
        float b1v = fc2b[m_base + mi * 16 + 8 + g];
#pragma unroll
        for (int ni = 0; ni < 4; ++ni) {
            acc2[mi][ni][0] = b0v; acc2[mi][ni][1] = b0v;
            acc2[mi][ni][2] = b1v; acc2[mi][ni][3] = b1v;
        }
    }

    for (int half = 0; half < 2; ++half) {
        stageW(fc1w + (size_t)half * CC * CC, CC, 0, sW, tid);
        __syncthreads();
        float acc1[3][4][4];
        zacc(acc1);
        mma_gemm(sW, sXnH, acc1, lane, m_base, n_base);
        __syncthreads();   // mma done before sW restage / sMH write visible ordering
        // bias + exact GELU -> sMH bf16
#pragma unroll
        for (int mi = 0; mi < 3; ++mi)
#pragma unroll
            for (int ni = 0; ni < 4; ++ni) {
                int r0 = m_base + mi * 16 + g, c = n_base + ni * 8 + t2;
                float b0v = fc1b[half * CC + r0];
                float b1v = fc1b[half * CC + r0 + 8];
                float x0 = acc1[mi][ni][0] + b0v, x1 = acc1[mi][ni][1] + b0v;
                float x2 = acc1[mi][ni][2] + b1v, x3 = acc1[mi][ni][3] + b1v;
                float g0 = 0.5f * x0 * (1.f + erff(x0 * 0.70710678118f));
                float g1 = 0.5f * x1 * (1.f + erff(x1 * 0.70710678118f));
                float g2 = 0.5f * x2 * (1.f + erff(x2 * 0.70710678118f));
                float g3 = 0.5f * x3 * (1.f + erff(x3 * 0.70710678118f));
                *(__nv_bfloat162*)&sMH[r0 * TNH + c]       = __floats2bfloat162_rn(g0, g1);
                *(__nv_bfloat162*)&sMH[(r0 + 8) * TNH + c] = __floats2bfloat162_rn(g2, g3);
            }
        stageW(fc2w, HID, half * CC, sW, tid);
        __syncthreads();
        mma_gemm(sW, sMH, acc2, lane, m_base, n_base);
        __syncthreads();   // before next half restages sW / rewrites sMH
    }

    // out = fused + mlp
#pragma unroll
    for (int mi = 0; mi < 3; ++mi)
#pragma unroll
        for (int ni = 0; ni < 4; ++ni) {
            int r0 = m_base + mi * 16 + g, c = n_base + ni * 8 + t2;
            float2 xr0 = *(const float2*)&sX[r0 * TS + c];
            float2 xr1 = *(const float2*)&sX[(r0 + 8) * TS + c];
            float2 o0 = make_float2(acc2[mi][ni][0] + xr0.x, acc2[mi][ni][1] + xr0.y);
            float2 o1 = make_float2(acc2[mi][ni][2] + xr1.x, acc2[mi][ni][3] + xr1.y);
            *(float2*)&out[((size_t)(b * CC + r0)) * HWs + p0 + c] = o0;
            *(float2*)&out[((size_t)(b * CC + r0 + 8)) * HWs + p0 + c] = o1;
        }
}

// -------------------- launch --------------------
extern "C" void kernel_launch(void* const* d_in, const int* in_sizes, int n_in,
                              void* d_out, int out_size)
{
    const float* image = (const float*)d_in[0];
    const float* mask  = (const float*)d_in[1];
    const float* n1w   = (const float*)d_in[2];
    const float* n1b   = (const float*)d_in[3];
    const float* Wq    = (const float*)d_in[4];
    const float* Wk    = (const float*)d_in[5];
    const float* Wv    = (const float*)d_in[6];
    const float* Wo    = (const float*)d_in[7];
    const float* temp  = (const float*)d_in[8];
    const float* n2w   = (const float*)d_in[9];
    const float* n2b   = (const float*)d_in[10];
    const float* fc1w  = (const float*)d_in[11];
    const float* fc1b  = (const float*)d_in[12];
    const float* fc2w  = (const float*)d_in[13];
    const float* fc2b  = (const float*)d_in[14];
    float* out = (float*)d_out;

    // smem sizes (bytes)
    size_t smem1  = (size_t)(CC * TS) * 4 + (size_t)(2 * CC * TNH) * 2
                  + (size_t)(CC * WST) * 2 + 640 * 4;
    size_t smem3a = (size_t)(2 * CC * TNH) * 2 + (size_t)(CC * WST) * 2
                  + (size_t)(HEADS * DH * DH) * 4;
    size_t smem3b = (size_t)(CC * TS) * 4 + (size_t)(2 * CC * TNH) * 2
                  + (size_t)(CC * WST) * 2 + 640 * 4;

    cudaFuncSetAttribute(k1,  cudaFuncAttributeMaxDynamicSharedMemorySize, (int)smem1);
    cudaFuncSetAttribute(k3a, cudaFuncAttributeMaxDynamicSharedMemorySize, (int)smem3a);
    cudaFuncSetAttribute(k3b, cudaFuncAttributeMaxDynamicSharedMemorySize, (int)smem3b);

    dim3 grid(HWs / TN, BB);

    k_zero<<<64, 256>>>();
    k1 <<<grid, 256, smem1 >>>(image, mask, n1w, n1b, Wq, Wk, Wv);
    k2 <<<BB * HEADS, 32>>>(temp);
    k3a<<<grid, 256, smem3a>>>(image, Wo);
    k3b<<<grid, 256, smem3b>>>(n2w, n2b, fc1w, fc1b, fc2w, fc2b, out);
}